// round 7
// baseline (speedup 1.0000x reference)
#include <cuda_runtime.h>
#include <cuda_bf16.h>
#include <cstdint>

#define BATCH 8
#define NN 2048
#define EE 2048

#define BM 256
#define BN 128
#define BK 64
#define STAGES 4
#define STAGE_BYTES 49152       // A: 256x128B (32KB) + B: 128x128B (16KB)
#define NBK 96                  // 3 phases x 32 k-blocks of 64

// ---------------- scratch globals (no cudaMalloc allowed) ----------------
__device__ __align__(256) __nv_bfloat16 g_xh[(size_t)BATCH * NN * EE];
__device__ __align__(256) __nv_bfloat16 g_xl[(size_t)BATCH * NN * EE];
__device__ __align__(256) __nv_bfloat16 g_wh[(size_t)EE * EE];
__device__ __align__(256) __nv_bfloat16 g_wl[(size_t)EE * EE];
__device__ __align__(256) __nv_bfloat16 g_qh[(size_t)BATCH * NN * EE];
__device__ __align__(256) __nv_bfloat16 g_ql[(size_t)BATCH * NN * EE];
__device__ __align__(256) __nv_bfloat16 g_ah[(size_t)BATCH * NN * NN];
__device__ __align__(256) __nv_bfloat16 g_al[(size_t)BATCH * NN * NN];
__device__ __align__(256) float         g_s [(size_t)BATCH * NN * NN];
__device__ __align__(256) float         g_cmax[BATCH * NN];
__device__ __align__(256) float         g_csum[BATCH * NN];

// ---------------- helpers ----------------
__device__ __forceinline__ uint32_t smem_u32(const void* p) {
    uint32_t a;
    asm("{ .reg .u64 t; cvta.to.shared.u64 t, %1; cvt.u32.u64 %0, t; }" : "=r"(a) : "l"(p));
    return a;
}
__device__ __forceinline__ void cp16(uint32_t s, const void* g) {
    asm volatile("cp.async.cg.shared.global [%0], [%1], 16;" :: "r"(s), "l"(g) : "memory");
}
__device__ __forceinline__ void cp_commit() {
    asm volatile("cp.async.commit_group;" ::: "memory");
}
template <int N> __device__ __forceinline__ void cp_wait() {
    asm volatile("cp.async.wait_group %0;" :: "n"(N) : "memory");
}
__device__ __forceinline__ void ldm4(uint32_t* r, uint32_t a) {
    asm volatile("ldmatrix.sync.aligned.m8n8.x4.shared.b16 {%0,%1,%2,%3}, [%4];"
                 : "=r"(r[0]), "=r"(r[1]), "=r"(r[2]), "=r"(r[3]) : "r"(a));
}
__device__ __forceinline__ void mma16816(float* c, const uint32_t* a, uint32_t b0, uint32_t b1) {
    asm volatile(
        "mma.sync.aligned.m16n8k16.row.col.f32.bf16.bf16.f32 "
        "{%0,%1,%2,%3}, {%4,%5,%6,%7}, {%8,%9}, {%0,%1,%2,%3};"
        : "+f"(c[0]), "+f"(c[1]), "+f"(c[2]), "+f"(c[3])
        : "r"(a[0]), "r"(a[1]), "r"(a[2]), "r"(a[3]), "r"(b0), "r"(b1));
}

// ---------------- persistent tensor-core GEMM: C tiles 256x128 = A @ B^T ----------------
// 3-phase bf16 split over K'=3*2048: Ah*Bh, Al*Bh, Ah*Bl.
// mode 0: write fp32 to outF. mode 1: split-store hi/lo bf16 to outH/outL.
// Persistent: grid = #SMs; CTA walks tiles t, t+grid, ...; next tile's first 3
// stages are prefetched during the last 3 k-blocks of the current tile.
__global__ __launch_bounds__(256, 1)
void gemm_mma(const __nv_bfloat16* Ah, const __nv_bfloat16* Al,
              const __nv_bfloat16* Bh, const __nv_bfloat16* Bl,
              long long aBatch, long long bBatch, long long cBatch,
              float* outF, __nv_bfloat16* outH, __nv_bfloat16* outL, int mode,
              int gx, int gy, int nTiles)
{
    extern __shared__ __align__(128) char smem[];
    const uint32_t stg0 = smem_u32(smem);
    const int tid  = threadIdx.x;
    const int lane = tid & 31;
    const int warp = tid >> 5;

    // -------- global->smem producer mapping (all 256 threads) --------
    const int lr = tid >> 3;        // 0..31 row group
    const int lc = tid & 7;         // 16B chunk within 128B row
    const uint32_t so = (uint32_t)(lr * 128 + ((lc ^ (lr & 7)) << 4));

    // -------- mma fragment addressing precompute --------
    const int wm  = warp & 3;            // 4 warps down M (64 rows each)
    const int wn  = warp >> 2;           // 2 warps across N (64 cols each)
    const int m0w = wm * 64;
    const int n0w = wn * 64;
    const uint32_t aRow  = (uint32_t)(m0w + (lane & 15));
    const uint32_t aBase = aRow * 128;
    const uint32_t aXor  = aRow & 7;
    const uint32_t ac0   = (uint32_t)(lane >> 4);
    const uint32_t bRow  = (uint32_t)(n0w + ((lane >> 4) << 3) + (lane & 7));
    const uint32_t bBase = 32768u + bRow * 128;
    const uint32_t bXor  = (uint32_t)(lane & 7);
    const uint32_t bc0   = (uint32_t)((lane >> 3) & 1);

    float acc[4][8][4] = {};
    uint32_t af[2][4][4], bf[2][4][4];   // double-buffered fragments

    // load-side pointers (switch to next tile 3 k-blocks early)
    const char *gAh, *gAl, *gBh, *gBl;
    auto setLoad = [&](int t) {
        const int bx = t % gx;
        const int r2 = t / gx;
        const int by = r2 % gy;
        const int bz = r2 / gy;
        gAh = (const char*)(Ah + (size_t)bz * (size_t)aBatch + (size_t)(by * BM + lr) * EE) + lc * 16;
        gAl = (const char*)(Al + (size_t)bz * (size_t)aBatch + (size_t)(by * BM + lr) * EE) + lc * 16;
        gBh = (const char*)(Bh + (size_t)bz * (size_t)bBatch + (size_t)(bx * BN + lr) * EE) + lc * 16;
        gBl = (const char*)(Bl + (size_t)bz * (size_t)bBatch + (size_t)(bx * BN + lr) * EE) + lc * 16;
    };

    // one quarter of a stage load (3 cp16 per thread); part 3 commits the group
    auto load_chunk = [&](int s, int kbn, int part) {
        const int p = kbn >> 5;
        const char* a = (p == 1) ? gAl : gAh;
        const char* b = (p == 2) ? gBl : gBh;
        const uint32_t koff = (uint32_t)(kbn & 31) * 128;
        const uint32_t dstA = stg0 + (uint32_t)s * STAGE_BYTES + so;
        const uint32_t dstB = dstA + 32768u;
        cp16(dstA + (uint32_t)(part * 2)     * 4096u, a + koff + (size_t)(part * 2)     * 131072);
        cp16(dstA + (uint32_t)(part * 2 + 1) * 4096u, a + koff + (size_t)(part * 2 + 1) * 131072);
        cp16(dstB + (uint32_t)part           * 4096u, b + koff + (size_t)part           * 131072);
        if (part == 3) cp_commit();
    };
    // fragment load for one ks into buffer bsel from stage base sb_
    auto ldm_ks = [&](uint32_t sb_, uint32_t ke, int bsel) {
#pragma unroll
        for (int mt = 0; mt < 4; mt++)
            ldm4(af[bsel][mt], sb_ + aBase + mt * 2048u + (((ke * 2 + ac0) ^ aXor) << 4));
#pragma unroll
        for (int np = 0; np < 4; np++)
            ldm4(bf[bsel][np], sb_ + bBase + np * 2048u + (((ke * 2 + bc0) ^ bXor) << 4));
    };

    int t = blockIdx.x;
    setLoad(t);
#pragma unroll
    for (int st = 0; st < 3; st++)
        for (int part = 0; part < 4; part++) load_chunk(st, st, part);
    cp_wait<1>();                 // stages 0 and 1 complete
    __syncthreads();
    ldm_ks(stg0, 0, 0);           // fragments for kb=0, ks=0

    for (;;) {
        // epilogue coords of the CURRENT tile
        const int bx = t % gx;
        const int r2 = t / gx;
        const int row0 = (r2 % gy) * BM;
        const int col0 = bx * BN;
        const int z    = r2 / gy;
        const bool hasNext = (t + (int)gridDim.x) < nTiles;

        for (int kb = 0; kb < NBK; kb++) {
            if (kb == NBK - 3 && hasNext) setLoad(t + (int)gridDim.x);
            const bool doLoad = (kb < NBK - 3) || hasNext;
            const int  kbn    = (kb + 3 < NBK) ? (kb + 3) : (kb + 3 - NBK);
            const uint32_t sb = stg0 + (uint32_t)(kb & 3) * STAGE_BYTES;
#pragma unroll
            for (int ks = 0; ks < 4; ks++) {
                if (doLoad) load_chunk((kb + 3) & 3, kbn, ks);
                const int cur = ks & 1;
                if (ks < 3)
                    ldm_ks(sb, (uint32_t)ks + 1, cur ^ 1);
                else if (kb + 1 < NBK)
                    ldm_ks(stg0 + (uint32_t)((kb + 1) & 3) * STAGE_BYTES, 0, cur ^ 1);
#pragma unroll
                for (int mt = 0; mt < 4; mt++)
#pragma unroll
                    for (int np = 0; np < 4; np++) {
                        mma16816(acc[mt][np * 2],     af[cur][mt], bf[cur][np][0], bf[cur][np][1]);
                        mma16816(acc[mt][np * 2 + 1], af[cur][mt], bf[cur][np][2], bf[cur][np][3]);
                    }
            }
            if (kb + 1 < NBK) {
                if (doLoad) cp_wait<1>(); else cp_wait<0>();
                __syncthreads();
            }
        }
        if (hasNext) cp_wait<1>(); else cp_wait<0>();
        __syncthreads();
        if (hasNext) ldm_ks(stg0, 0, 0);   // next tile kb0/ks0 fragments (stage 0)

        // -------- epilogue (overlaps with in-flight next-tile cp.async) --------
        const int g  = lane >> 2;
        const int tg = lane & 3;
        if (mode == 0) {
            float* base = outF + (size_t)z * (size_t)cBatch;
#pragma unroll
            for (int mt = 0; mt < 4; mt++) {
                const int rg = row0 + m0w + mt * 16 + g;
#pragma unroll
                for (int nt = 0; nt < 8; nt++) {
                    const int cg = col0 + n0w + nt * 8 + 2 * tg;
                    *(float2*)(base + (size_t)rg * 2048 + cg)       = make_float2(acc[mt][nt][0], acc[mt][nt][1]);
                    *(float2*)(base + (size_t)(rg + 8) * 2048 + cg) = make_float2(acc[mt][nt][2], acc[mt][nt][3]);
                }
            }
        } else {
#pragma unroll
            for (int mt = 0; mt < 4; mt++) {
                const int rg = row0 + m0w + mt * 16 + g;
#pragma unroll
                for (int nt = 0; nt < 8; nt++) {
                    const int cg = col0 + n0w + nt * 8 + 2 * tg;
                    float v[4] = {acc[mt][nt][0], acc[mt][nt][1], acc[mt][nt][2], acc[mt][nt][3]};
                    __nv_bfloat16 h0 = __float2bfloat16(v[0]), h1 = __float2bfloat16(v[1]);
                    __nv_bfloat16 h2 = __float2bfloat16(v[2]), h3 = __float2bfloat16(v[3]);
                    __nv_bfloat16 l0 = __float2bfloat16(v[0] - __bfloat162float(h0));
                    __nv_bfloat16 l1 = __float2bfloat16(v[1] - __bfloat162float(h1));
                    __nv_bfloat16 l2 = __float2bfloat16(v[2] - __bfloat162float(h2));
                    __nv_bfloat16 l3 = __float2bfloat16(v[3] - __bfloat162float(h3));
                    *(__nv_bfloat162*)(outH + (size_t)rg * 2048 + cg)       = __nv_bfloat162(h0, h1);
                    *(__nv_bfloat162*)(outL + (size_t)rg * 2048 + cg)       = __nv_bfloat162(l0, l1);
                    *(__nv_bfloat162*)(outH + (size_t)(rg + 8) * 2048 + cg) = __nv_bfloat162(h2, h3);
                    *(__nv_bfloat162*)(outL + (size_t)(rg + 8) * 2048 + cg) = __nv_bfloat162(l2, l3);
                }
            }
        }
        if (!hasNext) break;
#pragma unroll
        for (int mt = 0; mt < 4; mt++)
#pragma unroll
            for (int nt = 0; nt < 8; nt++)
#pragma unroll
                for (int q = 0; q < 4; q++) acc[mt][nt][q] = 0.0f;
        t += (int)gridDim.x;
    }
}

// ---------------- fp32 -> (bf16 hi, bf16 lo) split ----------------
__global__ void split_hl(const float* __restrict__ src,
                         __nv_bfloat16* __restrict__ h, __nv_bfloat16* __restrict__ l)
{
    const size_t i = ((size_t)blockIdx.x * blockDim.x + threadIdx.x) * 4;
    float4 v = *(const float4*)(src + i);
    __nv_bfloat16 h0 = __float2bfloat16(v.x), h1 = __float2bfloat16(v.y);
    __nv_bfloat16 h2 = __float2bfloat16(v.z), h3 = __float2bfloat16(v.w);
    *(__nv_bfloat162*)(h + i)     = __nv_bfloat162(h0, h1);
    *(__nv_bfloat162*)(h + i + 2) = __nv_bfloat162(h2, h3);
    *(__nv_bfloat162*)(l + i)     = __nv_bfloat162(__float2bfloat16(v.x - __bfloat162float(h0)),
                                                   __float2bfloat16(v.y - __bfloat162float(h1)));
    *(__nv_bfloat162*)(l + i + 2) = __nv_bfloat162(__float2bfloat16(v.z - __bfloat162float(h2)),
                                                   __float2bfloat16(v.w - __bfloat162float(h3)));
}

// ---------------- column softmax (axis=1) stats: coalesced via smem transpose ----------------
// Block: 256 threads handle a 256-column panel; rows streamed in 32-row tiles.
__global__ __launch_bounds__(256)
void col_stats(const float* __restrict__ S,
               float* __restrict__ cmax, float* __restrict__ crsum)
{
    __shared__ float tile[32][260];
    const int b  = blockIdx.y;
    const int c0 = blockIdx.x * 256;
    const int tid = threadIdx.x;
    const float* Sb = S + (size_t)b * NN * NN + c0;

    float m = -1e30f, s = 0.0f;
    for (int rt = 0; rt < NN / 32; rt++) {
        const float* base = Sb + (size_t)rt * 32 * NN;
#pragma unroll
        for (int i = 0; i < 8; i++) {
            const int idx = i * 256 + tid;            // 0..2047 float4 slots
            const int r   = idx >> 6;
            const int c4  = (idx & 63) << 2;
            *(float4*)&tile[r][c4] = *(const float4*)(base + (size_t)r * NN + c4);
        }
        __syncthreads();
#pragma unroll
        for (int r = 0; r < 32; r++) {
            const float v = tile[r][tid];
            if (v > m) {
                const float d = m - v;
                s = (d < -20.0f) ? 1.0f : s * __expf(d) + 1.0f;
                m = v;
            } else {
                const float d = v - m;
                if (d > -20.0f) s += __expf(d);   // skipped terms < e^-20: negligible
            }
        }
        __syncthreads();
    }
    cmax[b * NN + c0 + tid]  = m;
    crsum[b * NN + c0 + tid] = 1.0f / s;
}

__global__ void col_norm_split(const float* __restrict__ S,
                               const float* __restrict__ cmax, const float* __restrict__ crsum,
                               __nv_bfloat16* __restrict__ ah, __nv_bfloat16* __restrict__ al)
{
    const int b   = blockIdx.y;
    const int lin = blockIdx.x * blockDim.x + threadIdx.x;
    const int i   = lin >> 9;
    const int j4  = (lin & 511) << 2;
    const size_t off = (size_t)b * NN * NN + (size_t)i * NN + j4;

    float4 v  = *(const float4*)(S + off);
    float4 mx = *(const float4*)(cmax  + b * NN + j4);
    float4 rs = *(const float4*)(crsum + b * NN + j4);
    float a0 = __expf(v.x - mx.x) * rs.x;
    float a1 = __expf(v.y - mx.y) * rs.y;
    float a2 = __expf(v.z - mx.z) * rs.z;
    float a3 = __expf(v.w - mx.w) * rs.w;
    __nv_bfloat16 h0 = __float2bfloat16(a0), h1 = __float2bfloat16(a1);
    __nv_bfloat16 h2 = __float2bfloat16(a2), h3 = __float2bfloat16(a3);
    *(__nv_bfloat162*)(ah + off)     = __nv_bfloat162(h0, h1);
    *(__nv_bfloat162*)(ah + off + 2) = __nv_bfloat162(h2, h3);
    *(__nv_bfloat162*)(al + off)     = __nv_bfloat162(__float2bfloat16(a0 - __bfloat162float(h0)),
                                                      __float2bfloat16(a1 - __bfloat162float(h1)));
    *(__nv_bfloat162*)(al + off + 2) = __nv_bfloat162(__float2bfloat16(a2 - __bfloat162float(h2)),
                                                      __float2bfloat16(a3 - __bfloat162float(h3)));
}

// ---------------- launch ----------------
extern "C" void kernel_launch(void* const* d_in, const int* in_sizes, int n_in,
                              void* d_out, int out_size)
{
    const float* X = (const float*)d_in[0];
    const float* W = (const float*)d_in[1];
    // d_in[2] = bias: per-column constant on scores -> cancels in axis-1 softmax.
    // d_in[3] = gamma: scalar constant -> cancels likewise. Both unused.
    float* out = (float*)d_out;

    __nv_bfloat16 *xh, *xl, *wh, *wl, *qh, *ql, *ah, *al;
    float *s, *cmax, *csum;
    cudaGetSymbolAddress((void**)&xh, g_xh);  cudaGetSymbolAddress((void**)&xl, g_xl);
    cudaGetSymbolAddress((void**)&wh, g_wh);  cudaGetSymbolAddress((void**)&wl, g_wl);
    cudaGetSymbolAddress((void**)&qh, g_qh);  cudaGetSymbolAddress((void**)&ql, g_ql);
    cudaGetSymbolAddress((void**)&ah, g_ah);  cudaGetSymbolAddress((void**)&al, g_al);
    cudaGetSymbolAddress((void**)&s,  g_s);
    cudaGetSymbolAddress((void**)&cmax, g_cmax);
    cudaGetSymbolAddress((void**)&csum, g_csum);

    int dev = 0;  cudaGetDevice(&dev);
    int nsm = 148;
    cudaDeviceGetAttribute(&nsm, cudaDevAttrMultiProcessorCount, dev);

    const int smem = STAGES * STAGE_BYTES;   // 192 KB -> 1 CTA/SM
    cudaFuncSetAttribute(gemm_mma, cudaFuncAttributeMaxDynamicSharedMemorySize, smem);

    // split inputs into hi/lo bf16
    split_hl<<<(BATCH * NN * EE / 4) / 256, 256>>>(X, xh, xl);
    split_hl<<<(EE * EE / 4) / 256, 256>>>(W, wh, wl);

    const long long sXE = (long long)NN * EE;
    const long long sNN = (long long)NN * NN;

    // GEMM1: Q = X W^T -> hi/lo bf16 (qh, ql).  Tiles: gx=16, gy=64, gz=1.
    gemm_mma<<<nsm, 256, smem>>>(xh, xl, wh, wl, 0, 0, 0,
                                 nullptr, qh, ql, 1, 16, 64, 1024);

    // GEMM2: S[b] = Q[b] X[b]^T (fp32).  Tiles: gx=16, gy=8, gz=8.
    gemm_mma<<<nsm, 256, smem>>>(qh, ql, xh, xl, sXE, sXE, sNN,
                                 s, nullptr, nullptr, 0, 16, 8, 1024);

    // softmax over axis=1 (columns), then write split attn
    col_stats<<<dim3(NN / 256, BATCH), 256>>>(s, cmax, csum);
    col_norm_split<<<dim3((NN * NN / 4) / 256, BATCH), 256>>>(s, cmax, csum, ah, al);

    // GEMM3: out[b] = X[b] Attn[b]^T (fp32).  Tiles: gx=16, gy=8, gz=8.
    gemm_mma<<<nsm, 256, smem>>>(xh, xl, ah, al, sXE, sNN, sNN,
                                 out, nullptr, nullptr, 0, 16, 8, 1024);
}

// round 8
// speedup vs baseline: 1.2168x; 1.2168x over previous
#include <cuda_runtime.h>
#include <cuda_bf16.h>
#include <cuda_fp16.h>
#include <cstdint>

#define BATCH 8
#define NN 2048
#define EE 2048

#define BM 256
#define BN 128
#define BK 64
#define STAGES 4
#define STAGE_BYTES 49152       // A: 256x128B (32KB) + B: 128x128B (16KB)

// ---------------- scratch globals (no cudaMalloc allowed) ----------------
__device__ __align__(256) __nv_bfloat16 g_xh[(size_t)BATCH * NN * EE];
__device__ __align__(256) __nv_bfloat16 g_xl[(size_t)BATCH * NN * EE];
__device__ __align__(256) __half        g_xf[(size_t)BATCH * NN * EE];
__device__ __align__(256) __nv_bfloat16 g_wh[(size_t)EE * EE];
__device__ __align__(256) __nv_bfloat16 g_wl[(size_t)EE * EE];
__device__ __align__(256) __nv_bfloat16 g_qh[(size_t)BATCH * NN * EE];
__device__ __align__(256) __nv_bfloat16 g_ql[(size_t)BATCH * NN * EE];
__device__ __align__(256) __half        g_af[(size_t)BATCH * NN * NN];
__device__ __align__(256) float         g_s [(size_t)BATCH * NN * NN];
__device__ __align__(256) float         g_cmax[BATCH * NN];
__device__ __align__(256) float         g_csum[BATCH * NN];

// ---------------- helpers ----------------
__device__ __forceinline__ uint32_t smem_u32(const void* p) {
    uint32_t a;
    asm("{ .reg .u64 t; cvta.to.shared.u64 t, %1; cvt.u32.u64 %0, t; }" : "=r"(a) : "l"(p));
    return a;
}
__device__ __forceinline__ void cp16(uint32_t s, const void* g) {
    asm volatile("cp.async.cg.shared.global [%0], [%1], 16;" :: "r"(s), "l"(g) : "memory");
}
__device__ __forceinline__ void cp_commit() {
    asm volatile("cp.async.commit_group;" ::: "memory");
}
template <int N> __device__ __forceinline__ void cp_wait() {
    asm volatile("cp.async.wait_group %0;" :: "n"(N) : "memory");
}
__device__ __forceinline__ void ldm4(uint32_t* r, uint32_t a) {
    asm volatile("ldmatrix.sync.aligned.m8n8.x4.shared.b16 {%0,%1,%2,%3}, [%4];"
                 : "=r"(r[0]), "=r"(r[1]), "=r"(r[2]), "=r"(r[3]) : "r"(a));
}
template <bool F16>
__device__ __forceinline__ void mma16816(float* c, const uint32_t* a, uint32_t b0, uint32_t b1) {
    if (F16)
        asm volatile(
            "mma.sync.aligned.m16n8k16.row.col.f32.f16.f16.f32 "
            "{%0,%1,%2,%3}, {%4,%5,%6,%7}, {%8,%9}, {%0,%1,%2,%3};"
            : "+f"(c[0]), "+f"(c[1]), "+f"(c[2]), "+f"(c[3])
            : "r"(a[0]), "r"(a[1]), "r"(a[2]), "r"(a[3]), "r"(b0), "r"(b1));
    else
        asm volatile(
            "mma.sync.aligned.m16n8k16.row.col.f32.bf16.bf16.f32 "
            "{%0,%1,%2,%3}, {%4,%5,%6,%7}, {%8,%9}, {%0,%1,%2,%3};"
            : "+f"(c[0]), "+f"(c[1]), "+f"(c[2]), "+f"(c[3])
            : "r"(a[0]), "r"(a[1]), "r"(a[2]), "r"(a[3]), "r"(b0), "r"(b1));
}

// ---------------- persistent tensor-core GEMM: C tiles 256x128 = A @ B^T ----------------
// Phases over K' = nbk*64: kbn>>5 selects (Ah,Bh) / (Al,Bh) / (Ah,Bl).
// nbk=96: 3-phase split GEMM.  nbk=32: single-phase (Ah,Bh only).
// mode 0: write fp32 to outF. mode 1: split-store hi/lo bf16 to outH/outL.
template <bool F16>
__global__ __launch_bounds__(256, 1)
void gemm_mma(const void* Ahv, const void* Alv, const void* Bhv, const void* Blv,
              long long aBatch, long long bBatch, long long cBatch,
              float* outF, __nv_bfloat16* outH, __nv_bfloat16* outL, int mode,
              int gx, int gy, int nTiles, int nbk)
{
    extern __shared__ __align__(128) char smem[];
    const uint32_t stg0 = smem_u32(smem);
    const int tid  = threadIdx.x;
    const int lane = tid & 31;
    const int warp = tid >> 5;

    // -------- global->smem producer mapping (all 256 threads) --------
    const int lr = tid >> 3;        // 0..31 row group
    const int lc = tid & 7;         // 16B chunk within 128B row
    const uint32_t so = (uint32_t)(lr * 128 + ((lc ^ (lr & 7)) << 4));

    // -------- mma fragment addressing precompute --------
    const int wm  = warp & 3;            // 4 warps down M (64 rows each)
    const int wn  = warp >> 2;           // 2 warps across N (64 cols each)
    const int m0w = wm * 64;
    const int n0w = wn * 64;
    const uint32_t aRow  = (uint32_t)(m0w + (lane & 15));
    const uint32_t aBase = aRow * 128;
    const uint32_t aXor  = aRow & 7;
    const uint32_t ac0   = (uint32_t)(lane >> 4);
    const uint32_t bRow  = (uint32_t)(n0w + ((lane >> 4) << 3) + (lane & 7));
    const uint32_t bBase = 32768u + bRow * 128;
    const uint32_t bXor  = (uint32_t)(lane & 7);
    const uint32_t bc0   = (uint32_t)((lane >> 3) & 1);

    float acc[4][8][4] = {};
    uint32_t af[2][4][4], bf[2][4][4];   // double-buffered fragments

    // load-side pointers (switch to next tile 3 k-blocks early)
    const char *gAh, *gAl, *gBh, *gBl;
    auto setLoad = [&](int t) {
        const int bx = t % gx;
        const int r2 = t / gx;
        const int by = r2 % gy;
        const int bz = r2 / gy;
        const size_t aoff = ((size_t)bz * (size_t)aBatch + (size_t)(by * BM + lr) * EE) * 2 + lc * 16;
        const size_t boff = ((size_t)bz * (size_t)bBatch + (size_t)(bx * BN + lr) * EE) * 2 + lc * 16;
        gAh = (const char*)Ahv + aoff;
        gAl = (const char*)Alv + aoff;
        gBh = (const char*)Bhv + boff;
        gBl = (const char*)Blv + boff;
    };

    // one quarter of a stage load (3 cp16 per thread); part 3 commits the group
    auto load_chunk = [&](int s, int kbn, int part) {
        const int p = kbn >> 5;
        const char* a = (p == 1) ? gAl : gAh;
        const char* b = (p == 2) ? gBl : gBh;
        const uint32_t koff = (uint32_t)(kbn & 31) * 128;
        const uint32_t dstA = stg0 + (uint32_t)s * STAGE_BYTES + so;
        const uint32_t dstB = dstA + 32768u;
        cp16(dstA + (uint32_t)(part * 2)     * 4096u, a + koff + (size_t)(part * 2)     * 131072);
        cp16(dstA + (uint32_t)(part * 2 + 1) * 4096u, a + koff + (size_t)(part * 2 + 1) * 131072);
        cp16(dstB + (uint32_t)part           * 4096u, b + koff + (size_t)part           * 131072);
        if (part == 3) cp_commit();
    };
    // fragment load for one ks into buffer bsel from stage base sb_
    auto ldm_ks = [&](uint32_t sb_, uint32_t ke, int bsel) {
#pragma unroll
        for (int mt = 0; mt < 4; mt++)
            ldm4(af[bsel][mt], sb_ + aBase + mt * 2048u + (((ke * 2 + ac0) ^ aXor) << 4));
#pragma unroll
        for (int np = 0; np < 4; np++)
            ldm4(bf[bsel][np], sb_ + bBase + np * 2048u + (((ke * 2 + bc0) ^ bXor) << 4));
    };

    int t = blockIdx.x;
    if (t >= nTiles) return;
    setLoad(t);
#pragma unroll
    for (int st = 0; st < 3; st++)
        for (int part = 0; part < 4; part++) load_chunk(st, st, part);
    cp_wait<1>();                 // stages 0 and 1 complete
    __syncthreads();
    ldm_ks(stg0, 0, 0);           // fragments for kb=0, ks=0

    for (;;) {
        // epilogue coords of the CURRENT tile
        const int bx = t % gx;
        const int r2 = t / gx;
        const int row0 = (r2 % gy) * BM;
        const int col0 = bx * BN;
        const int z    = r2 / gy;
        const bool hasNext = (t + (int)gridDim.x) < nTiles;

        for (int kb = 0; kb < nbk; kb++) {
            if (kb == nbk - 3 && hasNext) setLoad(t + (int)gridDim.x);
            const bool doLoad = (kb < nbk - 3) || hasNext;
            const int  kbn    = (kb + 3 < nbk) ? (kb + 3) : (kb + 3 - nbk);
            const uint32_t sb = stg0 + (uint32_t)(kb & 3) * STAGE_BYTES;
#pragma unroll
            for (int ks = 0; ks < 4; ks++) {
                if (doLoad) load_chunk((kb + 3) & 3, kbn, ks);
                const int cur = ks & 1;
                if (ks < 3)
                    ldm_ks(sb, (uint32_t)ks + 1, cur ^ 1);
                else if (kb + 1 < nbk)
                    ldm_ks(stg0 + (uint32_t)((kb + 1) & 3) * STAGE_BYTES, 0, cur ^ 1);
#pragma unroll
                for (int mt = 0; mt < 4; mt++)
#pragma unroll
                    for (int np = 0; np < 4; np++) {
                        mma16816<F16>(acc[mt][np * 2],     af[cur][mt], bf[cur][np][0], bf[cur][np][1]);
                        mma16816<F16>(acc[mt][np * 2 + 1], af[cur][mt], bf[cur][np][2], bf[cur][np][3]);
                    }
            }
            if (kb + 1 < nbk) {
                if (doLoad) cp_wait<1>(); else cp_wait<0>();
                __syncthreads();
            }
        }
        if (hasNext) cp_wait<1>(); else cp_wait<0>();
        __syncthreads();
        if (hasNext) ldm_ks(stg0, 0, 0);   // next tile kb0/ks0 fragments (stage 0)

        // -------- epilogue (overlaps with in-flight next-tile cp.async) --------
        const int g  = lane >> 2;
        const int tg = lane & 3;
        if (mode == 0) {
            float* base = outF + (size_t)z * (size_t)cBatch;
#pragma unroll
            for (int mt = 0; mt < 4; mt++) {
                const int rg = row0 + m0w + mt * 16 + g;
#pragma unroll
                for (int nt = 0; nt < 8; nt++) {
                    const int cg = col0 + n0w + nt * 8 + 2 * tg;
                    *(float2*)(base + (size_t)rg * 2048 + cg)       = make_float2(acc[mt][nt][0], acc[mt][nt][1]);
                    *(float2*)(base + (size_t)(rg + 8) * 2048 + cg) = make_float2(acc[mt][nt][2], acc[mt][nt][3]);
                }
            }
        } else {
#pragma unroll
            for (int mt = 0; mt < 4; mt++) {
                const int rg = row0 + m0w + mt * 16 + g;
#pragma unroll
                for (int nt = 0; nt < 8; nt++) {
                    const int cg = col0 + n0w + nt * 8 + 2 * tg;
                    float v[4] = {acc[mt][nt][0], acc[mt][nt][1], acc[mt][nt][2], acc[mt][nt][3]};
                    __nv_bfloat16 h0 = __float2bfloat16(v[0]), h1 = __float2bfloat16(v[1]);
                    __nv_bfloat16 h2 = __float2bfloat16(v[2]), h3 = __float2bfloat16(v[3]);
                    __nv_bfloat16 l0 = __float2bfloat16(v[0] - __bfloat162float(h0));
                    __nv_bfloat16 l1 = __float2bfloat16(v[1] - __bfloat162float(h1));
                    __nv_bfloat16 l2 = __float2bfloat16(v[2] - __bfloat162float(h2));
                    __nv_bfloat16 l3 = __float2bfloat16(v[3] - __bfloat162float(h3));
                    *(__nv_bfloat162*)(outH + (size_t)rg * 2048 + cg)       = __nv_bfloat162(h0, h1);
                    *(__nv_bfloat162*)(outL + (size_t)rg * 2048 + cg)       = __nv_bfloat162(l0, l1);
                    *(__nv_bfloat162*)(outH + (size_t)(rg + 8) * 2048 + cg) = __nv_bfloat162(h2, h3);
                    *(__nv_bfloat162*)(outL + (size_t)(rg + 8) * 2048 + cg) = __nv_bfloat162(l2, l3);
                }
            }
        }
        if (!hasNext) break;
#pragma unroll
        for (int mt = 0; mt < 4; mt++)
#pragma unroll
            for (int nt = 0; nt < 8; nt++)
#pragma unroll
                for (int q = 0; q < 4; q++) acc[mt][nt][q] = 0.0f;
        t += (int)gridDim.x;
    }
}

// ---------------- fp32 -> (bf16 hi, bf16 lo [, fp16]) split ----------------
__global__ void split_hl(const float* __restrict__ src,
                         __nv_bfloat16* __restrict__ h, __nv_bfloat16* __restrict__ l,
                         __half* __restrict__ f)
{
    const size_t i = ((size_t)blockIdx.x * blockDim.x + threadIdx.x) * 4;
    float4 v = *(const float4*)(src + i);
    __nv_bfloat16 h0 = __float2bfloat16(v.x), h1 = __float2bfloat16(v.y);
    __nv_bfloat16 h2 = __float2bfloat16(v.z), h3 = __float2bfloat16(v.w);
    *(__nv_bfloat162*)(h + i)     = __nv_bfloat162(h0, h1);
    *(__nv_bfloat162*)(h + i + 2) = __nv_bfloat162(h2, h3);
    *(__nv_bfloat162*)(l + i)     = __nv_bfloat162(__float2bfloat16(v.x - __bfloat162float(h0)),
                                                   __float2bfloat16(v.y - __bfloat162float(h1)));
    *(__nv_bfloat162*)(l + i + 2) = __nv_bfloat162(__float2bfloat16(v.z - __bfloat162float(h2)),
                                                   __float2bfloat16(v.w - __bfloat162float(h3)));
    if (f) {
        *(__half2*)(f + i)     = __floats2half2_rn(v.x, v.y);
        *(__half2*)(f + i + 2) = __floats2half2_rn(v.z, v.w);
    }
}

// ---------------- column softmax (axis=1) stats: coalesced via smem transpose ----------------
__global__ __launch_bounds__(256)
void col_stats(const float* __restrict__ S,
               float* __restrict__ cmax, float* __restrict__ crsum)
{
    __shared__ float tile[32][260];
    const int b  = blockIdx.y;
    const int c0 = blockIdx.x * 256;
    const int tid = threadIdx.x;
    const float* Sb = S + (size_t)b * NN * NN + c0;

    float m = -1e30f, s = 0.0f;
    for (int rt = 0; rt < NN / 32; rt++) {
        const float* base = Sb + (size_t)rt * 32 * NN;
#pragma unroll
        for (int i = 0; i < 8; i++) {
            const int idx = i * 256 + tid;
            const int r   = idx >> 6;
            const int c4  = (idx & 63) << 2;
            *(float4*)&tile[r][c4] = *(const float4*)(base + (size_t)r * NN + c4);
        }
        __syncthreads();
#pragma unroll
        for (int r = 0; r < 32; r++) {
            const float v = tile[r][tid];
            if (v > m) {
                const float d = m - v;
                s = (d < -20.0f) ? 1.0f : s * __expf(d) + 1.0f;
                m = v;
            } else {
                const float d = v - m;
                if (d > -20.0f) s += __expf(d);
            }
        }
        __syncthreads();
    }
    cmax[b * NN + c0 + tid]  = m;
    crsum[b * NN + c0 + tid] = 1.0f / s;
}

// attn (fp16) = exp(S - cmax[j]) * crsum[j]
__global__ void col_norm_f16(const float* __restrict__ S,
                             const float* __restrict__ cmax, const float* __restrict__ crsum,
                             __half* __restrict__ af)
{
    const int b   = blockIdx.y;
    const int lin = blockIdx.x * blockDim.x + threadIdx.x;
    const int i   = lin >> 9;
    const int j4  = (lin & 511) << 2;
    const size_t off = (size_t)b * NN * NN + (size_t)i * NN + j4;

    float4 v  = *(const float4*)(S + off);
    float4 mx = *(const float4*)(cmax  + b * NN + j4);
    float4 rs = *(const float4*)(crsum + b * NN + j4);
    float a0 = __expf(v.x - mx.x) * rs.x;
    float a1 = __expf(v.y - mx.y) * rs.y;
    float a2 = __expf(v.z - mx.z) * rs.z;
    float a3 = __expf(v.w - mx.w) * rs.w;
    *(__half2*)(af + off)     = __floats2half2_rn(a0, a1);
    *(__half2*)(af + off + 2) = __floats2half2_rn(a2, a3);
}

// ---------------- launch ----------------
extern "C" void kernel_launch(void* const* d_in, const int* in_sizes, int n_in,
                              void* d_out, int out_size)
{
    const float* X = (const float*)d_in[0];
    const float* W = (const float*)d_in[1];
    // d_in[2] = bias: per-column constant on scores -> cancels in axis-1 softmax.
    // d_in[3] = gamma: scalar constant -> cancels likewise. Both unused.
    float* out = (float*)d_out;

    __nv_bfloat16 *xh, *xl, *wh, *wl, *qh, *ql;
    __half *xf, *afp;
    float *s, *cmax, *csum;
    cudaGetSymbolAddress((void**)&xh, g_xh);  cudaGetSymbolAddress((void**)&xl, g_xl);
    cudaGetSymbolAddress((void**)&xf, g_xf);
    cudaGetSymbolAddress((void**)&wh, g_wh);  cudaGetSymbolAddress((void**)&wl, g_wl);
    cudaGetSymbolAddress((void**)&qh, g_qh);  cudaGetSymbolAddress((void**)&ql, g_ql);
    cudaGetSymbolAddress((void**)&afp, g_af);
    cudaGetSymbolAddress((void**)&s,  g_s);
    cudaGetSymbolAddress((void**)&cmax, g_cmax);
    cudaGetSymbolAddress((void**)&csum, g_csum);

    int dev = 0;  cudaGetDevice(&dev);
    int nsm = 148;
    cudaDeviceGetAttribute(&nsm, cudaDevAttrMultiProcessorCount, dev);

    const int smem = STAGES * STAGE_BYTES;   // 192 KB -> 1 CTA/SM
    cudaFuncSetAttribute(gemm_mma<false>, cudaFuncAttributeMaxDynamicSharedMemorySize, smem);
    cudaFuncSetAttribute(gemm_mma<true>,  cudaFuncAttributeMaxDynamicSharedMemorySize, smem);

    // split inputs: X -> bf16 hi/lo + fp16; W -> bf16 hi/lo
    split_hl<<<(BATCH * NN * EE / 4) / 256, 256>>>(X, xh, xl, xf);
    split_hl<<<(EE * EE / 4) / 256, 256>>>(W, wh, wl, nullptr);

    const long long sXE = (long long)NN * EE;
    const long long sNN = (long long)NN * NN;

    // GEMM1: Q = X W^T -> hi/lo bf16. 3-phase bf16. Tiles: gx=16, gy=64.
    gemm_mma<false><<<nsm, 256, smem>>>(xh, xl, wh, wl, 0, 0, 0,
                                        nullptr, qh, ql, 1, 16, 64, 1024, 96);

    // GEMM2: S[b] = Q[b] X[b]^T (fp32). 3-phase bf16. Tiles: gx=16, gy=8, gz=8.
    gemm_mma<false><<<nsm, 256, smem>>>(qh, ql, xh, xl, sXE, sXE, sNN,
                                        s, nullptr, nullptr, 0, 16, 8, 1024, 96);

    // softmax over axis=1 (columns), write fp16 attn
    col_stats<<<dim3(NN / 256, BATCH), 256>>>(s, cmax, csum);
    col_norm_f16<<<dim3((NN * NN / 4) / 256, BATCH), 256>>>(s, cmax, csum, afp);

    // GEMM3: out[b] = X[b] Attn[b]^T (fp32). SINGLE-phase fp16 (downstream of
    // softmax: fp16 rounding of X and attn gives ~2e-4 global rel err).
    gemm_mma<true><<<nsm, 256, smem>>>(xf, xf, afp, afp, sXE, sNN, sNN,
                                       out, nullptr, nullptr, 0, 16, 8, 1024, 32);
}